// round 15
// baseline (speedup 1.0000x reference)
#include <cuda_runtime.h>
#include <cstdint>

// ---------------------------------------------------------------------------
// QuanvolutionClassifier, phase form:
//   logits[b,c] = bias[c] + sum_px (w[c,px]*R_w) * cos(x[b,px] - phi_w)
// Round 15: staging via coalesced LDG.128 -> STS.128 (breaks the LDGSTS
// 16B/8cyc issue floor that capped streaming at ~1.5TB/s). Barrier-free
// compute. SAMP=56 / SPLIT=4 -> grid 588 = one wave at 4 CTAs/SM.
// ---------------------------------------------------------------------------

#define THREADS 256
#define WARPS 8
#define SPLIT 4
#define PX_CTA 196
#define NF4 49                         // float4 per x row (196 floats = 784 B)
#define ROWB 784
#define SAMP 56
#define MAXB 8192
#define NGRP_MAX 256

#define SX_BYTES (SAMP * ROWB)         // 43904 B (x tile first, aligned)
#define SW_FLOATS (PX_CTA * 12)        // 2352 floats = 9408 B
#define SMEM_BYTES (SX_BYTES + SW_FLOATS * 4)   // 53312

__device__ float g_part[SPLIT][MAXB][10];
__device__ unsigned int g_flag[NGRP_MAX];

typedef unsigned long long u64;

__device__ __forceinline__ u64 pack2(float x, float y) {
    u64 r; asm("mov.b64 %0, {%1, %2};" : "=l"(r) : "f"(x), "f"(y)); return r;
}
__device__ __forceinline__ u64 fma2(u64 a, u64 b, u64 c) {
    u64 d; asm("fma.rn.f32x2 %0, %1, %2, %3;" : "=l"(d) : "l"(a), "l"(b), "l"(c)); return d;
}
__device__ __forceinline__ float2 unpack2(u64 v) {
    float2 f; asm("mov.b64 {%0, %1}, %2;" : "=f"(f.x), "=f"(f.y) : "l"(v)); return f;
}

struct c2f { float x, y; };
__device__ __forceinline__ c2f cmulf(c2f a, c2f b) {
    return { a.x * b.x - a.y * b.y, a.x * b.y + a.y * b.x };
}

// ---------------------------------------------------------------------------
__global__ void __launch_bounds__(THREADS, 4)
quanv_kernel(const float* __restrict__ x,
             const float* __restrict__ params,
             const float* __restrict__ wmat,
             const float* __restrict__ bias,
             float* __restrict__ out,
             int B, int depth) {
    extern __shared__ float smem[];
    float* sXf = smem;                                 // SAMP rows x 784 B
    float* sW  = smem + SX_BYTES / 4;                  // PX_CTA*12
    float* sP  = smem;                                 // partials overlay on x
    __shared__ float sRP[8];                           // R[4], phi[4]
    __shared__ unsigned int sArriv;

    int tid = threadIdx.x;
    int warp = tid >> 5, lane = tid & 31;
    int part = blockIdx.x & (SPLIT - 1);
    int grp  = blockIdx.x >> 2;
    int b0 = grp * SAMP;
    int pxBase = part * PX_CTA;

    // ---- 1. stage x: warp w rows [7w, 7w+7). Coalesced LDG.128 + STS.128 ----
    // Row layout in gmem: 784 contiguous bytes. lanes 0-31 -> f4 cols 0-31,
    // lanes 0-16 -> f4 cols 32-48. Stores contiguous => conflict-free.
    {
        bool h1 = (lane < NF4 - 32);   // lane < 17
#pragma unroll
        for (int t = 0; t < 7; ++t) {
            int s = warp * 7 + t;
            int b = b0 + s; if (b >= B) b = B - 1;
            const float4* src = reinterpret_cast<const float4*>(
                x + (size_t)b * 784 + pxBase);
            float4 v0 = __ldg(src + lane);
            float4 v1 = h1 ? __ldg(src + 32 + lane)
                           : make_float4(0.f, 0.f, 0.f, 0.f);
            float4* drow = reinterpret_cast<float4*>(
                reinterpret_cast<char*>(sXf) + (size_t)s * ROWB);
            drow[lane] = v0;
            if (h1) drow[32 + lane] = v1;
        }
    }

    // ---- 2. wires 0..3: SU(2) composition -> (R, phi) ----
    if (tid < 4) {
        int wire = tid;
        c2f a0{1.f, 0.f}, b0c{0.f, 0.f};
        c2f a1{0.f, 0.f}, b1{1.f, 0.f};
        for (int d = 0; d < depth; ++d) {
            float rz1 = __ldg(&params[(d * 4 + wire) * 3 + 0]);
            float ry  = __ldg(&params[(d * 4 + wire) * 3 + 1]);
            float rz2 = __ldg(&params[(d * 4 + wire) * 3 + 2]);
            float c1v, s1v; __sincosf(0.5f * rz1, &s1v, &c1v);
            c2f p1{c1v, -s1v}, p1c{c1v, s1v};
            a0 = cmulf(a0, p1);  a1 = cmulf(a1, p1);
            b0c = cmulf(b0c, p1c); b1 = cmulf(b1, p1c);
            float cy, sy; __sincosf(0.5f * ry, &sy, &cy);
            c2f na0{cy * a0.x - sy * b0c.x, cy * a0.y - sy * b0c.y};
            c2f nb0{sy * a0.x + cy * b0c.x, sy * a0.y + cy * b0c.y};
            c2f na1{cy * a1.x - sy * b1.x, cy * a1.y - sy * b1.y};
            c2f nb1{sy * a1.x + cy * b1.x, sy * a1.y + cy * b1.y};
            a0 = na0; b0c = nb0; a1 = na1; b1 = nb1;
            float cz, sz; __sincosf(0.5f * rz2, &sz, &cz);
            c2f p2{cz, -sz}, p2c{cz, sz};
            a0 = cmulf(a0, p2);  a1 = cmulf(a1, p2);
            b0c = cmulf(b0c, p2c); b1 = cmulf(b1, p2c);
        }
        float al = 2.f * (a0.x * a0.x + a0.y * a0.y) - 1.f;
        float be = 2.f * (a0.x * a1.x + a0.y * a1.y);
        sRP[wire]     = sqrtf(al * al + be * be);
        sRP[4 + wire] = atan2f(be, al);
    }

    // ---- 3. wmat gather: one pixel per thread (tid < 196), 10 channels ----
    float wv[10];
    int wi = 0;
    if (tid < PX_CTA) {
        int gpx = pxBase + tid;
        int r = gpx / 28, cc = gpx - r * 28;
        wi = (r & 1) * 2 + (cc & 1);
        int kidx = ((r >> 1) * 14 + (cc >> 1)) * 4 + wi;
#pragma unroll
        for (int c = 0; c < 10; ++c)
            wv[c] = __ldg(&wmat[c * 784 + kidx]);
    }
    __syncthreads();   // sRP ready; x STS visible

    // ---- 4. fold weights (w*R) + phi into smem ----
    if (tid < PX_CTA) {
        float R  = sRP[wi];
        float ph = sRP[4 + wi];
        float* wr = sW + tid * 12;
#pragma unroll
        for (int c = 0; c < 10; ++c) wr[c] = wv[c] * R;
        wr[10] = ph;
        wr[11] = 0.f;
    }
    __syncthreads();   // sW ready

    // ---- 5. compute (barrier-free): warp w quads j = w, w+8, ... ----
    u64 accA[5] = {0ull, 0ull, 0ull, 0ull, 0ull};
    u64 accB[5] = {0ull, 0ull, 0ull, 0ull, 0ull};
    const float4* xrowA = reinterpret_cast<const float4*>(
        reinterpret_cast<char*>(sXf) + (size_t)lane * ROWB);
    const float4* xrowB = reinterpret_cast<const float4*>(
        reinterpret_cast<char*>(sXf) + (size_t)(lane + 32) * ROWB);
    bool hasB = (lane < 24);

#define PROC_PX(pa, pb, pxi)                                                 \
    {                                                                        \
        const ulonglong2* wp =                                               \
            reinterpret_cast<const ulonglong2*>(sW + (pxi) * 12);            \
        ulonglong2 q0 = wp[0], q1 = wp[1], q2 = wp[2];                       \
        float2 ph = unpack2(q2.y);                                           \
        float za = __cosf((pa) - ph.x);                                      \
        float zb = __cosf((pb) - ph.x);                                      \
        u64 zza = pack2(za, za);                                             \
        u64 zzb = pack2(zb, zb);                                             \
        accA[0] = fma2(q0.x, zza, accA[0]);                                  \
        accB[0] = fma2(q0.x, zzb, accB[0]);                                  \
        accA[1] = fma2(q0.y, zza, accA[1]);                                  \
        accB[1] = fma2(q0.y, zzb, accB[1]);                                  \
        accA[2] = fma2(q1.x, zza, accA[2]);                                  \
        accB[2] = fma2(q1.x, zzb, accB[2]);                                  \
        accA[3] = fma2(q1.y, zza, accA[3]);                                  \
        accB[3] = fma2(q1.y, zzb, accB[3]);                                  \
        accA[4] = fma2(q2.x, zza, accA[4]);                                  \
        accB[4] = fma2(q2.x, zzb, accB[4]);                                  \
    }

#pragma unroll
    for (int t = 0; t < 6; ++t) {
        int j = warp + 8 * t;
        float4 xa = xrowA[j];
        float4 xb = hasB ? xrowB[j] : xa;
        int pxl = j * 4;
        PROC_PX(xa.x, xb.x, pxl + 0);
        PROC_PX(xa.y, xb.y, pxl + 1);
        PROC_PX(xa.z, xb.z, pxl + 2);
        PROC_PX(xa.w, xb.w, pxl + 3);
    }
    if (warp == 0) {      // j = 48 tail
        float4 xa = xrowA[48];
        float4 xb = hasB ? xrowB[48] : xa;
        PROC_PX(xa.x, xb.x, 192);
        PROC_PX(xa.y, xb.y, 193);
        PROC_PX(xa.z, xb.z, 194);
        PROC_PX(xa.w, xb.w, 195);
    }
#undef PROC_PX

    // ---- 6. per-warp partials -> smem (overlay on x, protected by sync) ----
    __syncthreads();
    {
        float2* ppA = reinterpret_cast<float2*>(sP + (warp * SAMP + lane) * 10);
#pragma unroll
        for (int j = 0; j < 5; ++j) ppA[j] = unpack2(accA[j]);
        if (hasB) {
            float2* ppB = reinterpret_cast<float2*>(sP + (warp * SAMP + lane + 32) * 10);
#pragma unroll
            for (int j = 0; j < 5; ++j) ppB[j] = unpack2(accB[j]);
        }
    }
    __syncthreads();

    // ---- 7. reduce 8 warps -> global partial scratch ----
    for (int idx = tid; idx < SAMP * 10; idx += THREADS) {
        int s = idx / 10, c = idx - s * 10;
        float v = 0.f;
#pragma unroll
        for (int w = 0; w < WARPS; ++w) v += sP[(w * SAMP + s) * 10 + c];
        int b = b0 + s;
        if (b < B && b < MAXB) g_part[part][b][c] = v;
    }

    // ---- 8. completion counter: last CTA of group finalizes ----
    __threadfence();
    __syncthreads();
    if (tid == 0) sArriv = atomicAdd(&g_flag[grp], 1u);
    __syncthreads();
    if (sArriv == SPLIT - 1) {
        if (tid < SAMP) {
            int b = b0 + tid;
            if (b < B) {
                float L[10];
#pragma unroll
                for (int c = 0; c < 10; ++c) {
                    float v = __ldg(&bias[c]);
#pragma unroll
                    for (int p = 0; p < SPLIT; ++p) v += __ldcg(&g_part[p][b][c]);
                    L[c] = v;
                }
                float m = L[0];
#pragma unroll
                for (int c = 1; c < 10; ++c) m = fmaxf(m, L[c]);
                float sum = 0.f;
#pragma unroll
                for (int c = 0; c < 10; ++c) sum += __expf(L[c] - m);
                float lse = m + __logf(sum);
#pragma unroll
                for (int c = 0; c < 10; ++c) out[(size_t)b * 10 + c] = L[c] - lse;
            }
        }
        if (tid == 0) g_flag[grp] = 0u;
    }
}

extern "C" void kernel_launch(void* const* d_in, const int* in_sizes, int n_in,
                              void* d_out, int out_size) {
    const float* x      = (const float*)d_in[0];
    const float* params = (const float*)d_in[1];
    const float* wmat   = (const float*)d_in[2];
    const float* bias   = (const float*)d_in[3];
    float* out = (float*)d_out;

    int B = in_sizes[0] / 784;
    int depth = in_sizes[1] / 12;

    cudaFuncSetAttribute(quanv_kernel,
                         cudaFuncAttributeMaxDynamicSharedMemorySize, SMEM_BYTES);

    int ngroups = (B + SAMP - 1) / SAMP;
    quanv_kernel<<<ngroups * SPLIT, THREADS, SMEM_BYTES>>>(
        x, params, wmat, bias, out, B, depth);
}

// round 16
// speedup vs baseline: 1.0288x; 1.0288x over previous
#include <cuda_runtime.h>
#include <cstdint>

// ---------------------------------------------------------------------------
// QuanvolutionClassifier, phase form:
//   logits[b,c] = bias[c] + sum_px (w[c,px]*R_w) * cos(x[b,px] - phi_w)
// Round 16: R15 (LDG.128->STS staging) + L2::evict_last cache-policy on the
// x LDGs (load-path hint, unlike R13's ignored async-copy hint) so x stays
// L2-resident across graph replays: 577cyc DRAM -> ~250cyc L2 per miss,
// ~2.3x the per-SM latency-limited stream rate.
// ---------------------------------------------------------------------------

#define THREADS 256
#define WARPS 8
#define SPLIT 4
#define PX_CTA 196
#define NF4 49                         // float4 per x row (196 floats = 784 B)
#define ROWB 784
#define SAMP 56
#define MAXB 8192
#define NGRP_MAX 256

#define SX_BYTES (SAMP * ROWB)         // 43904 B (x tile first, aligned)
#define SW_FLOATS (PX_CTA * 12)        // 2352 floats = 9408 B
#define SMEM_BYTES (SX_BYTES + SW_FLOATS * 4)   // 53312

__device__ float g_part[SPLIT][MAXB][10];
__device__ unsigned int g_flag[NGRP_MAX];

typedef unsigned long long u64;

__device__ __forceinline__ u64 pack2(float x, float y) {
    u64 r; asm("mov.b64 %0, {%1, %2};" : "=l"(r) : "f"(x), "f"(y)); return r;
}
__device__ __forceinline__ u64 fma2(u64 a, u64 b, u64 c) {
    u64 d; asm("fma.rn.f32x2 %0, %1, %2, %3;" : "=l"(d) : "l"(a), "l"(b), "l"(c)); return d;
}
__device__ __forceinline__ float2 unpack2(u64 v) {
    float2 f; asm("mov.b64 {%0, %1}, %2;" : "=f"(f.x), "=f"(f.y) : "l"(v)); return f;
}
// x load with L2 evict_last policy (keeps x resident in L2 across replays)
__device__ __forceinline__ float4 ldg_el(const float4* p, u64 pol) {
    float4 v;
    asm volatile("ld.global.nc.L2::cache_hint.v4.f32 {%0,%1,%2,%3}, [%4], %5;"
                 : "=f"(v.x), "=f"(v.y), "=f"(v.z), "=f"(v.w)
                 : "l"(p), "l"(pol));
    return v;
}

struct c2f { float x, y; };
__device__ __forceinline__ c2f cmulf(c2f a, c2f b) {
    return { a.x * b.x - a.y * b.y, a.x * b.y + a.y * b.x };
}

// ---------------------------------------------------------------------------
__global__ void __launch_bounds__(THREADS, 4)
quanv_kernel(const float* __restrict__ x,
             const float* __restrict__ params,
             const float* __restrict__ wmat,
             const float* __restrict__ bias,
             float* __restrict__ out,
             int B, int depth) {
    extern __shared__ float smem[];
    float* sXf = smem;                                 // SAMP rows x 784 B
    float* sW  = smem + SX_BYTES / 4;                  // PX_CTA*12
    float* sP  = smem;                                 // partials overlay on x
    __shared__ float sRP[8];                           // R[4], phi[4]
    __shared__ unsigned int sArriv;

    int tid = threadIdx.x;
    int warp = tid >> 5, lane = tid & 31;
    int part = blockIdx.x & (SPLIT - 1);
    int grp  = blockIdx.x >> 2;
    int b0 = grp * SAMP;
    int pxBase = part * PX_CTA;

    // evict_last policy for the x stream
    u64 pol;
    asm("createpolicy.fractional.L2::evict_last.b64 %0, 1.0;" : "=l"(pol));

    // ---- 1. stage x: warp w rows [7w, 7w+7). Coalesced LDG.128 + STS.128 ----
    {
        bool h1 = (lane < NF4 - 32);   // lane < 17
#pragma unroll
        for (int t = 0; t < 7; ++t) {
            int s = warp * 7 + t;
            int b = b0 + s; if (b >= B) b = B - 1;
            const float4* src = reinterpret_cast<const float4*>(
                x + (size_t)b * 784 + pxBase);
            float4 v0 = ldg_el(src + lane, pol);
            float4 v1 = h1 ? ldg_el(src + 32 + lane, pol)
                           : make_float4(0.f, 0.f, 0.f, 0.f);
            float4* drow = reinterpret_cast<float4*>(
                reinterpret_cast<char*>(sXf) + (size_t)s * ROWB);
            drow[lane] = v0;
            if (h1) drow[32 + lane] = v1;
        }
    }

    // ---- 2. wires 0..3: SU(2) composition -> (R, phi) ----
    if (tid < 4) {
        int wire = tid;
        c2f a0{1.f, 0.f}, b0c{0.f, 0.f};
        c2f a1{0.f, 0.f}, b1{1.f, 0.f};
        for (int d = 0; d < depth; ++d) {
            float rz1 = __ldg(&params[(d * 4 + wire) * 3 + 0]);
            float ry  = __ldg(&params[(d * 4 + wire) * 3 + 1]);
            float rz2 = __ldg(&params[(d * 4 + wire) * 3 + 2]);
            float c1v, s1v; __sincosf(0.5f * rz1, &s1v, &c1v);
            c2f p1{c1v, -s1v}, p1c{c1v, s1v};
            a0 = cmulf(a0, p1);  a1 = cmulf(a1, p1);
            b0c = cmulf(b0c, p1c); b1 = cmulf(b1, p1c);
            float cy, sy; __sincosf(0.5f * ry, &sy, &cy);
            c2f na0{cy * a0.x - sy * b0c.x, cy * a0.y - sy * b0c.y};
            c2f nb0{sy * a0.x + cy * b0c.x, sy * a0.y + cy * b0c.y};
            c2f na1{cy * a1.x - sy * b1.x, cy * a1.y - sy * b1.y};
            c2f nb1{sy * a1.x + cy * b1.x, sy * a1.y + cy * b1.y};
            a0 = na0; b0c = nb0; a1 = na1; b1 = nb1;
            float cz, sz; __sincosf(0.5f * rz2, &sz, &cz);
            c2f p2{cz, -sz}, p2c{cz, sz};
            a0 = cmulf(a0, p2);  a1 = cmulf(a1, p2);
            b0c = cmulf(b0c, p2c); b1 = cmulf(b1, p2c);
        }
        float al = 2.f * (a0.x * a0.x + a0.y * a0.y) - 1.f;
        float be = 2.f * (a0.x * a1.x + a0.y * a1.y);
        sRP[wire]     = sqrtf(al * al + be * be);
        sRP[4 + wire] = atan2f(be, al);
    }

    // ---- 3. wmat gather: one pixel per thread (tid < 196), 10 channels ----
    float wv[10];
    int wi = 0;
    if (tid < PX_CTA) {
        int gpx = pxBase + tid;
        int r = gpx / 28, cc = gpx - r * 28;
        wi = (r & 1) * 2 + (cc & 1);
        int kidx = ((r >> 1) * 14 + (cc >> 1)) * 4 + wi;
#pragma unroll
        for (int c = 0; c < 10; ++c)
            wv[c] = __ldg(&wmat[c * 784 + kidx]);
    }
    __syncthreads();   // sRP ready; x STS visible

    // ---- 4. fold weights (w*R) + phi into smem ----
    if (tid < PX_CTA) {
        float R  = sRP[wi];
        float ph = sRP[4 + wi];
        float* wr = sW + tid * 12;
#pragma unroll
        for (int c = 0; c < 10; ++c) wr[c] = wv[c] * R;
        wr[10] = ph;
        wr[11] = 0.f;
    }
    __syncthreads();   // sW ready

    // ---- 5. compute (barrier-free): warp w quads j = w, w+8, ... ----
    u64 accA[5] = {0ull, 0ull, 0ull, 0ull, 0ull};
    u64 accB[5] = {0ull, 0ull, 0ull, 0ull, 0ull};
    const float4* xrowA = reinterpret_cast<const float4*>(
        reinterpret_cast<char*>(sXf) + (size_t)lane * ROWB);
    const float4* xrowB = reinterpret_cast<const float4*>(
        reinterpret_cast<char*>(sXf) + (size_t)(lane + 32) * ROWB);
    bool hasB = (lane < 24);

#define PROC_PX(pa, pb, pxi)                                                 \
    {                                                                        \
        const ulonglong2* wp =                                               \
            reinterpret_cast<const ulonglong2*>(sW + (pxi) * 12);            \
        ulonglong2 q0 = wp[0], q1 = wp[1], q2 = wp[2];                       \
        float2 ph = unpack2(q2.y);                                           \
        float za = __cosf((pa) - ph.x);                                      \
        float zb = __cosf((pb) - ph.x);                                      \
        u64 zza = pack2(za, za);                                             \
        u64 zzb = pack2(zb, zb);                                             \
        accA[0] = fma2(q0.x, zza, accA[0]);                                  \
        accB[0] = fma2(q0.x, zzb, accB[0]);                                  \
        accA[1] = fma2(q0.y, zza, accA[1]);                                  \
        accB[1] = fma2(q0.y, zzb, accB[1]);                                  \
        accA[2] = fma2(q1.x, zza, accA[2]);                                  \
        accB[2] = fma2(q1.x, zzb, accB[2]);                                  \
        accA[3] = fma2(q1.y, zza, accA[3]);                                  \
        accB[3] = fma2(q1.y, zzb, accB[3]);                                  \
        accA[4] = fma2(q2.x, zza, accA[4]);                                  \
        accB[4] = fma2(q2.x, zzb, accB[4]);                                  \
    }

#pragma unroll
    for (int t = 0; t < 6; ++t) {
        int j = warp + 8 * t;
        float4 xa = xrowA[j];
        float4 xb = hasB ? xrowB[j] : xa;
        int pxl = j * 4;
        PROC_PX(xa.x, xb.x, pxl + 0);
        PROC_PX(xa.y, xb.y, pxl + 1);
        PROC_PX(xa.z, xb.z, pxl + 2);
        PROC_PX(xa.w, xb.w, pxl + 3);
    }
    if (warp == 0) {      // j = 48 tail
        float4 xa = xrowA[48];
        float4 xb = hasB ? xrowB[48] : xa;
        PROC_PX(xa.x, xb.x, 192);
        PROC_PX(xa.y, xb.y, 193);
        PROC_PX(xa.z, xb.z, 194);
        PROC_PX(xa.w, xb.w, 195);
    }
#undef PROC_PX

    // ---- 6. per-warp partials -> smem (overlay on x, protected by sync) ----
    __syncthreads();
    {
        float2* ppA = reinterpret_cast<float2*>(sP + (warp * SAMP + lane) * 10);
#pragma unroll
        for (int j = 0; j < 5; ++j) ppA[j] = unpack2(accA[j]);
        if (hasB) {
            float2* ppB = reinterpret_cast<float2*>(sP + (warp * SAMP + lane + 32) * 10);
#pragma unroll
            for (int j = 0; j < 5; ++j) ppB[j] = unpack2(accB[j]);
        }
    }
    __syncthreads();

    // ---- 7. reduce 8 warps -> global partial scratch ----
    for (int idx = tid; idx < SAMP * 10; idx += THREADS) {
        int s = idx / 10, c = idx - s * 10;
        float v = 0.f;
#pragma unroll
        for (int w = 0; w < WARPS; ++w) v += sP[(w * SAMP + s) * 10 + c];
        int b = b0 + s;
        if (b < B && b < MAXB) g_part[part][b][c] = v;
    }

    // ---- 8. completion counter: last CTA of group finalizes ----
    __threadfence();
    __syncthreads();
    if (tid == 0) sArriv = atomicAdd(&g_flag[grp], 1u);
    __syncthreads();
    if (sArriv == SPLIT - 1) {
        if (tid < SAMP) {
            int b = b0 + tid;
            if (b < B) {
                float L[10];
#pragma unroll
                for (int c = 0; c < 10; ++c) {
                    float v = __ldg(&bias[c]);
#pragma unroll
                    for (int p = 0; p < SPLIT; ++p) v += __ldcg(&g_part[p][b][c]);
                    L[c] = v;
                }
                float m = L[0];
#pragma unroll
                for (int c = 1; c < 10; ++c) m = fmaxf(m, L[c]);
                float sum = 0.f;
#pragma unroll
                for (int c = 0; c < 10; ++c) sum += __expf(L[c] - m);
                float lse = m + __logf(sum);
#pragma unroll
                for (int c = 0; c < 10; ++c) out[(size_t)b * 10 + c] = L[c] - lse;
            }
        }
        if (tid == 0) g_flag[grp] = 0u;
    }
}

extern "C" void kernel_launch(void* const* d_in, const int* in_sizes, int n_in,
                              void* d_out, int out_size) {
    const float* x      = (const float*)d_in[0];
    const float* params = (const float*)d_in[1];
    const float* wmat   = (const float*)d_in[2];
    const float* bias   = (const float*)d_in[3];
    float* out = (float*)d_out;

    int B = in_sizes[0] / 784;
    int depth = in_sizes[1] / 12;

    cudaFuncSetAttribute(quanv_kernel,
                         cudaFuncAttributeMaxDynamicSharedMemorySize, SMEM_BYTES);

    int ngroups = (B + SAMP - 1) / SAMP;
    quanv_kernel<<<ngroups * SPLIT, THREADS, SMEM_BYTES>>>(
        x, params, wmat, bias, out, B, depth);
}

// round 17
// speedup vs baseline: 1.1577x; 1.1253x over previous
#include <cuda_runtime.h>
#include <cstdint>

// ---------------------------------------------------------------------------
// QuanvolutionClassifier, phase form:
//   logits[b,c] = bias[c] + sum_px (w[c,px]*R_w) * cos(x[b,px] - phi_w)
// Round 17: two tiles per CTA with register-carried prefetch — tile1's LDGs
// are issued before tile0's compute and held in regs, so DRAM drains during
// compute (phases overlap instead of summing). grid 294 = one wave at
// 2 CTAs/SM, 128 regs. Batched LDG.128->STS staging (deep MLP).
// ---------------------------------------------------------------------------

#define THREADS 256
#define WARPS 8
#define SPLIT 4
#define PX_CTA 196
#define NF4 49                         // float4 per x row (196 floats = 784 B)
#define ROWB 784
#define SAMP 56
#define MAXB 8192
#define NGRP_MAX 256

#define SX_FLOATS (SAMP * PX_CTA)      // 10976 floats = 43904 B
#define SW_FLOATS (PX_CTA * 12)        // 2352 floats  = 9408 B
#define SP_FLOATS (WARPS * SAMP * 10)  // 4480 floats  = 17920 B
#define SMEM_BYTES ((SX_FLOATS + SW_FLOATS + SP_FLOATS) * 4)   // 71232

__device__ float g_part[SPLIT][MAXB][10];
__device__ unsigned int g_flag[NGRP_MAX];

typedef unsigned long long u64;

__device__ __forceinline__ u64 pack2(float x, float y) {
    u64 r; asm("mov.b64 %0, {%1, %2};" : "=l"(r) : "f"(x), "f"(y)); return r;
}
__device__ __forceinline__ u64 fma2(u64 a, u64 b, u64 c) {
    u64 d; asm("fma.rn.f32x2 %0, %1, %2, %3;" : "=l"(d) : "l"(a), "l"(b), "l"(c)); return d;
}
__device__ __forceinline__ float2 unpack2(u64 v) {
    float2 f; asm("mov.b64 {%0, %1}, %2;" : "=f"(f.x), "=f"(f.y) : "l"(v)); return f;
}

struct c2f { float x, y; };
__device__ __forceinline__ c2f cmulf(c2f a, c2f b) {
    return { a.x * b.x - a.y * b.y, a.x * b.y + a.y * b.x };
}

// ---------------------------------------------------------------------------
__global__ void __launch_bounds__(THREADS, 2)
quanv_kernel(const float* __restrict__ x,
             const float* __restrict__ params,
             const float* __restrict__ wmat,
             const float* __restrict__ bias,
             float* __restrict__ out,
             int B, int depth, int ngrps) {
    extern __shared__ float smem[];
    float* sXf = smem;                       // SAMP x 784 B
    float* sW  = smem + SX_FLOATS;           // PX_CTA*12
    float* sP  = smem + SX_FLOATS + SW_FLOATS;
    __shared__ float sRP[8];                 // R[4], phi[4]
    __shared__ unsigned int sArriv;

    int tid = threadIdx.x;
    int warp = tid >> 5, lane = tid & 31;
    int t0 = 2 * blockIdx.x, t1 = t0 + 1;
    int part0 = t0 / ngrps, grp0 = t0 - part0 * ngrps;
    int part1 = t1 / ngrps, grp1 = t1 - part1 * ngrps;
    int b00 = grp0 * SAMP, b01 = grp1 * SAMP;
    int pxB0 = part0 * PX_CTA, pxB1 = part1 * PX_CTA;
    bool h1 = (lane < NF4 - 32);             // lane < 17

    // ---- 1. LDG tile0 (batched: all 14 loads/warp in flight) ----
    float4 a0[7], a1[7];
#pragma unroll
    for (int r = 0; r < 7; ++r) {
        int s = warp * 7 + r;
        int b = b00 + s; if (b >= B) b = B - 1;
        const float4* src = reinterpret_cast<const float4*>(
            x + (size_t)b * 784 + pxB0);
        a0[r] = __ldg(src + lane);
        a1[r] = h1 ? __ldg(src + 32 + lane) : make_float4(0.f, 0.f, 0.f, 0.f);
    }

    // ---- 2. wmat gather for part0 (overlaps tile0 LDG latency) ----
    float wv[10];
    int wi = 0;
    if (tid < PX_CTA) {
        int gpx = pxB0 + tid;
        int r = gpx / 28, cc = gpx - r * 28;
        wi = (r & 1) * 2 + (cc & 1);
        int kidx = ((r >> 1) * 14 + (cc >> 1)) * 4 + wi;
#pragma unroll
        for (int c = 0; c < 10; ++c)
            wv[c] = __ldg(&wmat[c * 784 + kidx]);
    }

    // ---- 3. wires 0..3: SU(2) composition -> (R, phi) ----
    if (tid < 4) {
        int wire = tid;
        c2f A0{1.f, 0.f}, B0{0.f, 0.f};
        c2f A1{0.f, 0.f}, B1{1.f, 0.f};
        for (int d = 0; d < depth; ++d) {
            float rz1 = __ldg(&params[(d * 4 + wire) * 3 + 0]);
            float ry  = __ldg(&params[(d * 4 + wire) * 3 + 1]);
            float rz2 = __ldg(&params[(d * 4 + wire) * 3 + 2]);
            float c1v, s1v; __sincosf(0.5f * rz1, &s1v, &c1v);
            c2f p1{c1v, -s1v}, p1c{c1v, s1v};
            A0 = cmulf(A0, p1);  A1 = cmulf(A1, p1);
            B0 = cmulf(B0, p1c); B1 = cmulf(B1, p1c);
            float cy, sy; __sincosf(0.5f * ry, &sy, &cy);
            c2f nA0{cy * A0.x - sy * B0.x, cy * A0.y - sy * B0.y};
            c2f nB0{sy * A0.x + cy * B0.x, sy * A0.y + cy * B0.y};
            c2f nA1{cy * A1.x - sy * B1.x, cy * A1.y - sy * B1.y};
            c2f nB1{sy * A1.x + cy * B1.x, sy * A1.y + cy * B1.y};
            A0 = nA0; B0 = nB0; A1 = nA1; B1 = nB1;
            float cz, sz; __sincosf(0.5f * rz2, &sz, &cz);
            c2f p2{cz, -sz}, p2c{cz, sz};
            A0 = cmulf(A0, p2);  A1 = cmulf(A1, p2);
            B0 = cmulf(B0, p2c); B1 = cmulf(B1, p2c);
        }
        float al = 2.f * (A0.x * A0.x + A0.y * A0.y) - 1.f;
        float be = 2.f * (A0.x * A1.x + A0.y * A1.y);
        sRP[wire]     = sqrtf(al * al + be * be);
        sRP[4 + wire] = atan2f(be, al);
    }

    // ---- 4. STS tile0 (frees a0/a1) ----
#pragma unroll
    for (int r = 0; r < 7; ++r) {
        int s = warp * 7 + r;
        float4* drow = reinterpret_cast<float4*>(
            reinterpret_cast<char*>(sXf) + (size_t)s * ROWB);
        drow[lane] = a0[r];
        if (h1) drow[32 + lane] = a1[r];
    }

    // ---- 5. LDG tile1 into the SAME regs; held through tile0 compute ----
#pragma unroll
    for (int r = 0; r < 7; ++r) {
        int s = warp * 7 + r;
        int b = b01 + s; if (b >= B) b = B - 1;
        const float4* src = reinterpret_cast<const float4*>(
            x + (size_t)b * 784 + pxB1);
        a0[r] = __ldg(src + lane);
        a1[r] = h1 ? __ldg(src + 32 + lane) : make_float4(0.f, 0.f, 0.f, 0.f);
    }

    __syncthreads();   // tile0 in smem, sRP ready

    // ---- 6. fold weights part0 ----
    if (tid < PX_CTA) {
        float R  = sRP[wi];
        float ph = sRP[4 + wi];
        float* wr = sW + tid * 12;
#pragma unroll
        for (int c = 0; c < 10; ++c) wr[c] = wv[c] * R;
        wr[10] = ph;
        wr[11] = 0.f;
    }

    // ---- 7. gather wv for part1 (if different) — in flight during compute ----
    if (part1 != part0 && tid < PX_CTA) {
        int gpx = pxB1 + tid;
        int r = gpx / 28, cc = gpx - r * 28;
        wi = (r & 1) * 2 + (cc & 1);
        int kidx = ((r >> 1) * 14 + (cc >> 1)) * 4 + wi;
#pragma unroll
        for (int c = 0; c < 10; ++c)
            wv[c] = __ldg(&wmat[c * 784 + kidx]);
    }
    __syncthreads();   // sW ready

    // ---- compute macro (phase-form inner loop, 2-sample blocking) ----
    u64 accA[5], accB[5];
    const float4* xrowA = reinterpret_cast<const float4*>(
        reinterpret_cast<char*>(sXf) + (size_t)lane * ROWB);
    const float4* xrowB = reinterpret_cast<const float4*>(
        reinterpret_cast<char*>(sXf) + (size_t)(lane + 32) * ROWB);
    bool hasB = (lane < 24);

#define PROC_PX(pa, pb, pxi)                                                 \
    {                                                                        \
        const ulonglong2* wp =                                               \
            reinterpret_cast<const ulonglong2*>(sW + (pxi) * 12);            \
        ulonglong2 q0 = wp[0], q1 = wp[1], q2 = wp[2];                       \
        float2 ph = unpack2(q2.y);                                           \
        float za = __cosf((pa) - ph.x);                                      \
        float zb = __cosf((pb) - ph.x);                                      \
        u64 zza = pack2(za, za);                                             \
        u64 zzb = pack2(zb, zb);                                             \
        accA[0] = fma2(q0.x, zza, accA[0]);                                  \
        accB[0] = fma2(q0.x, zzb, accB[0]);                                  \
        accA[1] = fma2(q0.y, zza, accA[1]);                                  \
        accB[1] = fma2(q0.y, zzb, accB[1]);                                  \
        accA[2] = fma2(q1.x, zza, accA[2]);                                  \
        accB[2] = fma2(q1.x, zzb, accB[2]);                                  \
        accA[3] = fma2(q1.y, zza, accA[3]);                                  \
        accB[3] = fma2(q1.y, zzb, accB[3]);                                  \
        accA[4] = fma2(q2.x, zza, accA[4]);                                  \
        accB[4] = fma2(q2.x, zzb, accB[4]);                                  \
    }

#define COMPUTE_TILE()                                                       \
    {                                                                        \
        _Pragma("unroll")                                                    \
        for (int j5 = 0; j5 < 5; ++j5) { accA[j5] = 0ull; accB[j5] = 0ull; } \
        _Pragma("unroll")                                                    \
        for (int t = 0; t < 6; ++t) {                                        \
            int j = warp + 8 * t;                                            \
            float4 xa = xrowA[j];                                            \
            float4 xb = hasB ? xrowB[j] : xa;                                \
            int pxl = j * 4;                                                 \
            PROC_PX(xa.x, xb.x, pxl + 0);                                    \
            PROC_PX(xa.y, xb.y, pxl + 1);                                    \
            PROC_PX(xa.z, xb.z, pxl + 2);                                    \
            PROC_PX(xa.w, xb.w, pxl + 3);                                    \
        }                                                                    \
        if (warp == 0) {                                                     \
            float4 xa = xrowA[48];                                           \
            float4 xb = hasB ? xrowB[48] : xa;                               \
            PROC_PX(xa.x, xb.x, 192);                                        \
            PROC_PX(xa.y, xb.y, 193);                                        \
            PROC_PX(xa.z, xb.z, 194);                                        \
            PROC_PX(xa.w, xb.w, 195);                                        \
        }                                                                    \
    }

#define WRITE_PARTIALS()                                                     \
    {                                                                        \
        float2* ppA = reinterpret_cast<float2*>(sP + (warp * SAMP + lane) * 10); \
        _Pragma("unroll")                                                    \
        for (int j5 = 0; j5 < 5; ++j5) ppA[j5] = unpack2(accA[j5]);          \
        if (hasB) {                                                          \
            float2* ppB = reinterpret_cast<float2*>(sP + (warp * SAMP + lane + 32) * 10); \
            _Pragma("unroll")                                                \
            for (int j5 = 0; j5 < 5; ++j5) ppB[j5] = unpack2(accB[j5]);      \
        }                                                                    \
    }

#define REDUCE_AND_FINALIZE(PART, GRP, B0V)                                  \
    {                                                                        \
        for (int idx = tid; idx < SAMP * 10; idx += THREADS) {               \
            int s = idx / 10, c = idx - s * 10;                              \
            float v = 0.f;                                                   \
            _Pragma("unroll")                                                \
            for (int w = 0; w < WARPS; ++w) v += sP[(w * SAMP + s) * 10 + c];\
            int b = (B0V) + s;                                               \
            if (b < B && b < MAXB) g_part[PART][b][c] = v;                   \
        }                                                                    \
        __threadfence();                                                     \
        __syncthreads();                                                     \
        if (tid == 0) sArriv = atomicAdd(&g_flag[GRP], 1u);                  \
        __syncthreads();                                                     \
        if (sArriv == SPLIT - 1) {                                           \
            if (tid < SAMP) {                                                \
                int b = (B0V) + tid;                                         \
                if (b < B) {                                                 \
                    float L[10];                                             \
                    _Pragma("unroll")                                        \
                    for (int c = 0; c < 10; ++c) {                           \
                        float v = __ldg(&bias[c]);                           \
                        _Pragma("unroll")                                    \
                        for (int p = 0; p < SPLIT; ++p)                      \
                            v += __ldcg(&g_part[p][b][c]);                   \
                        L[c] = v;                                            \
                    }                                                        \
                    float m = L[0];                                          \
                    _Pragma("unroll")                                        \
                    for (int c = 1; c < 10; ++c) m = fmaxf(m, L[c]);         \
                    float sum = 0.f;                                         \
                    _Pragma("unroll")                                        \
                    for (int c = 0; c < 10; ++c) sum += __expf(L[c] - m);    \
                    float lse = m + __logf(sum);                             \
                    _Pragma("unroll")                                        \
                    for (int c = 0; c < 10; ++c)                             \
                        out[(size_t)b * 10 + c] = L[c] - lse;                \
                }                                                            \
            }                                                                \
            if (tid == 0) g_flag[GRP] = 0u;                                  \
        }                                                                    \
    }

    // ---- 8. compute tile0 ----
    COMPUTE_TILE();
    WRITE_PARTIALS();
    __syncthreads();   // partials visible; compute t0 done reading sXf/sW

    // ---- 9. STS tile1 + refold (if needed), alongside tile0 reduce ----
#pragma unroll
    for (int r = 0; r < 7; ++r) {
        int s = warp * 7 + r;
        float4* drow = reinterpret_cast<float4*>(
            reinterpret_cast<char*>(sXf) + (size_t)s * ROWB);
        drow[lane] = a0[r];
        if (h1) drow[32 + lane] = a1[r];
    }
    if (part1 != part0 && tid < PX_CTA) {
        float R  = sRP[wi];
        float ph = sRP[4 + wi];
        float* wr = sW + tid * 12;
#pragma unroll
        for (int c = 0; c < 10; ++c) wr[c] = wv[c] * R;
        wr[10] = ph;
        wr[11] = 0.f;
    }
    REDUCE_AND_FINALIZE(part0, grp0, b00);
    __syncthreads();   // tile1 smem + sW ready; sP free for tile1

    // ---- 10. compute tile1 ----
    COMPUTE_TILE();
    WRITE_PARTIALS();
    __syncthreads();
    REDUCE_AND_FINALIZE(part1, grp1, b01);

#undef PROC_PX
#undef COMPUTE_TILE
#undef WRITE_PARTIALS
#undef REDUCE_AND_FINALIZE
}

extern "C" void kernel_launch(void* const* d_in, const int* in_sizes, int n_in,
                              void* d_out, int out_size) {
    const float* x      = (const float*)d_in[0];
    const float* params = (const float*)d_in[1];
    const float* wmat   = (const float*)d_in[2];
    const float* bias   = (const float*)d_in[3];
    float* out = (float*)d_out;

    int B = in_sizes[0] / 784;
    int depth = in_sizes[1] / 12;

    cudaFuncSetAttribute(quanv_kernel,
                         cudaFuncAttributeMaxDynamicSharedMemorySize, SMEM_BYTES);

    int ngrps = (B + SAMP - 1) / SAMP;          // 147 for B=8192
    int ntiles = ngrps * SPLIT;                 // 588 (always even)
    quanv_kernel<<<ntiles / 2, THREADS, SMEM_BYTES>>>(
        x, params, wmat, bias, out, B, depth, ngrps);
}